// round 3
// baseline (speedup 1.0000x reference)
#include <cuda_runtime.h>
#include <cuda_bf16.h>

#define BB 32
#define TT 1024
#define HH 384
#define MM 4096
#define PACE 1.0f
#define H4 (HH/4)          // 96 float4 per row
#define FPB 16             // frames per block in the main kernel

__device__ int    g_csum[BB * TT];
__device__ int    g_declen[BB];
__device__ float4 g_fA[BB * MM];   // {p[-1], p[0], p[+1], idx-as-bits}
__device__ float4 g_fB[BB * MM];   // {e[-1], e[0], e[+1], live-as-bits}

// ---------------------------------------------------------------------------
// Kernel 1: per-batch inclusive scan of reps (warp-shuffle scan), dec_lens
// ---------------------------------------------------------------------------
__global__ void scan_kernel(const int* __restrict__ dur,
                            float* __restrict__ out_tail /* may be null */)
{
    __shared__ int wsum[32];
    const int b = blockIdx.x;
    const int t = threadIdx.x;
    const int lane = t & 31;
    const int w = t >> 5;

    int v = (int)rintf((float)dur[b * TT + t] / PACE);

#pragma unroll
    for (int o = 1; o < 32; o <<= 1) {
        int n = __shfl_up_sync(0xFFFFFFFFu, v, o);
        if (lane >= o) v += n;
    }
    if (lane == 31) wsum[w] = v;
    __syncthreads();
    if (w == 0) {
        int s = wsum[lane];
#pragma unroll
        for (int o = 1; o < 32; o <<= 1) {
            int n = __shfl_up_sync(0xFFFFFFFFu, s, o);
            if (lane >= o) s += n;
        }
        wsum[lane] = s;
    }
    __syncthreads();
    int c = v + (w > 0 ? wsum[w - 1] : 0);
    g_csum[b * TT + t] = c;
    if (t == TT - 1) {
        int dl = min(c, MM);
        g_declen[b] = dl;
        if (out_tail) out_tail[b] = (float)dl;
    }
}

// ---------------------------------------------------------------------------
// Kernel 2: per-frame metadata — binary search + 6 pitch/energy scalars
// ---------------------------------------------------------------------------
__global__ __launch_bounds__(256)
void frame_kernel(const float* __restrict__ pitch,
                  const float* __restrict__ energy)
{
    const int gid = blockIdx.x * blockDim.x + threadIdx.x;   // b*MM + j
    if (gid >= BB * MM) return;
    const int b = gid >> 12;        // /MM
    const int j = gid & (MM - 1);

    const int* __restrict__ c = g_csum + b * TT;
    int lo = 0, hi = TT;
#pragma unroll 10
    while (lo < hi) {
        int mid = (lo + hi) >> 1;
        if (__ldg(c + mid) <= j) lo = mid + 1; else hi = mid;
    }
    const int idx  = min(lo, TT - 1);
    const int live = (j < g_declen[b]) ? 1 : 0;

    float pm1 = 0.f, p0 = 0.f, pp1 = 0.f;
    float em1 = 0.f, e0 = 0.f, ep1 = 0.f;
    if (live) {
        const float* P = pitch  + b * TT;
        const float* E = energy + b * TT;
        p0 = __ldg(P + idx);
        e0 = __ldg(E + idx);
        if (idx > 0)      { pm1 = __ldg(P + idx - 1); em1 = __ldg(E + idx - 1); }
        if (idx < TT - 1) { pp1 = __ldg(P + idx + 1); ep1 = __ldg(E + idx + 1); }
    }
    g_fA[gid] = make_float4(pm1, p0, pp1, __int_as_float(idx));
    g_fB[gid] = make_float4(em1, e0, ep1, __int_as_float(live));
}

// ---------------------------------------------------------------------------
// Kernel 3: fused conv-add + length-regulate gather, fully streaming.
// Thread = one float4 H-column; block covers 16 frames; no shared, no syncs.
// ---------------------------------------------------------------------------
__global__ __launch_bounds__(H4)
void regulate_kernel(const float* __restrict__ enc,
                     const float* __restrict__ pw,
                     const float* __restrict__ pb,
                     const float* __restrict__ ew,
                     const float* __restrict__ eb,
                     float* __restrict__ out)
{
    const int b   = blockIdx.y;
    const int j0  = blockIdx.x * FPB;
    const int tid = threadIdx.x;        // column in [0, 96)
    const int h   = tid * 4;

    // Register-resident conv weights for the 4 owned channels.
    float w0[4], w1[4], w2[4], w3[4], w4[4], w5[4], cb[4];
#pragma unroll
    for (int c = 0; c < 4; c++) {
        w0[c] = __ldg(pw + (h + c) * 3 + 0);
        w1[c] = __ldg(pw + (h + c) * 3 + 1);
        w2[c] = __ldg(pw + (h + c) * 3 + 2);
        w3[c] = __ldg(ew + (h + c) * 3 + 0);
        w4[c] = __ldg(ew + (h + c) * 3 + 1);
        w5[c] = __ldg(ew + (h + c) * 3 + 2);
        cb[c] = __ldg(pb + h + c) + __ldg(eb + h + c);
    }

    const float4* __restrict__ enc4 = (const float4*)enc;
    const float4* __restrict__ fA   = g_fA + b * MM + j0;
    const float4* __restrict__ fB   = g_fB + b * MM + j0;
    float4* __restrict__ out4 = (float4*)out + ((long long)b * MM + j0) * H4 + tid;
    const long long encbase = (long long)b * TT * H4 + tid;

#pragma unroll 4
    for (int f = 0; f < FPB; f++) {
        const float4 a = __ldg(fA + f);
        const float4 s = __ldg(fB + f);
        float4 r = make_float4(0.f, 0.f, 0.f, 0.f);
        if (__float_as_int(s.w)) {
            const int idx = __float_as_int(a.w);
            const float4 e4 = __ldg(enc4 + encbase + (long long)idx * H4);
            r.x = e4.x + cb[0] + a.x*w0[0] + a.y*w1[0] + a.z*w2[0]
                               + s.x*w3[0] + s.y*w4[0] + s.z*w5[0];
            r.y = e4.y + cb[1] + a.x*w0[1] + a.y*w1[1] + a.z*w2[1]
                               + s.x*w3[1] + s.y*w4[1] + s.z*w5[1];
            r.z = e4.z + cb[2] + a.x*w0[2] + a.y*w1[2] + a.z*w2[2]
                               + s.x*w3[2] + s.y*w4[2] + s.z*w5[2];
            r.w = e4.w + cb[3] + a.x*w0[3] + a.y*w1[3] + a.z*w2[3]
                               + s.x*w3[3] + s.y*w4[3] + s.z*w5[3];
        }
        __stcs(out4 + f * H4, r);   // streaming store: don't pollute L2
    }
}

// ---------------------------------------------------------------------------
extern "C" void kernel_launch(void* const* d_in, const int* in_sizes, int n_in,
                              void* d_out, int out_size)
{
    const float* enc    = (const float*)d_in[0];
    const float* pitch  = (const float*)d_in[1];
    const float* energy = (const float*)d_in[2];
    const float* pw     = (const float*)d_in[3];
    const float* pb     = (const float*)d_in[4];
    const float* ew     = (const float*)d_in[5];
    const float* eb     = (const float*)d_in[6];
    const int*   dur    = (const int*)d_in[7];

    float* out = (float*)d_out;

    const long long main_elems = (long long)BB * MM * HH;
    float* tail = ((long long)out_size >= main_elems + BB)
                      ? out + (out_size - BB) : nullptr;

    scan_kernel<<<BB, TT>>>(dur, tail);

    frame_kernel<<<(BB * MM + 255) / 256, 256>>>(pitch, energy);

    dim3 grid(MM / FPB, BB);
    regulate_kernel<<<grid, H4>>>(enc, pw, pb, ew, eb, out);
}